// round 8
// baseline (speedup 1.0000x reference)
#include <cuda_runtime.h>

#define TT 2048
#define NB 512
#define FULLM 0xFFFFFFFFu
typedef unsigned long long ull;

__device__ __forceinline__ float tanhap(float x) {
    float r; asm("tanh.approx.f32 %0, %1;" : "=f"(r) : "f"(x)); return r;
}
__device__ __forceinline__ ull pk(float lo, float hi) {
    ull r; asm("mov.b64 %0, {%1, %2};" : "=l"(r) : "f"(lo), "f"(hi)); return r;
}
__device__ __forceinline__ void upk(ull v, float& lo, float& hi) {
    asm("mov.b64 {%0, %1}, %2;" : "=f"(lo), "=f"(hi) : "l"(v));
}
__device__ __forceinline__ ull fma2(ull a, ull b, ull c) {
    ull d; asm("fma.rn.f32x2 %0, %1, %2, %3;" : "=l"(d) : "l"(a), "l"(b), "l"(c)); return d;
}
__device__ __forceinline__ ull add2(ull a, ull b) {
    ull d; asm("add.rn.f32x2 %0, %1, %2;" : "=l"(d) : "l"(a), "l"(b)); return d;
}
__device__ __forceinline__ ull d2l(double d) { return (ull)__double_as_longlong(d); }

__device__ __forceinline__ void cp_async4(void* smem_dst, const void* gmem_src) {
    unsigned saddr = (unsigned)__cvta_generic_to_shared(smem_dst);
    asm volatile("cp.async.ca.shared.global [%0], [%1], 4;\n"
                 :: "r"(saddr), "l"(gmem_src) : "memory");
}
__device__ __forceinline__ void cp_commit() {
    asm volatile("cp.async.commit_group;\n" ::: "memory");
}
__device__ __forceinline__ void cp_wait1() {
    asm volatile("cp.async.wait_group 1;\n" ::: "memory");
}

// Ordered h-row access: asm with memory clobber pins compiler order; same-warp
// shared ops retire in issue order through the in-order LSU pipe.
__device__ __forceinline__ void sts_h(unsigned addr, float v) {
    asm volatile("st.shared.f32 [%0], %1;" :: "r"(addr), "f"(v) : "memory");
}
__device__ __forceinline__ void lds_hpairs(unsigned a, ull* p) {
    asm volatile("ld.shared.v2.u64 {%0, %1}, [%2];"
                 : "=l"(p[0]), "=l"(p[1]) : "r"(a) : "memory");
    asm volatile("ld.shared.v2.u64 {%0, %1}, [%2+16];"
                 : "=l"(p[2]), "=l"(p[3]) : "r"(a) : "memory");
    asm volatile("ld.shared.v2.u64 {%0, %1}, [%2+32];"
                 : "=l"(p[4]), "=l"(p[5]) : "r"(a) : "memory");
    asm volatile("ld.shared.b64 %0, [%1+48];"
                 : "=l"(p[6]) : "r"(a) : "memory");
}

__global__ void __launch_bounds__(32)
lstm_warpseq6(const float* __restrict__ x,
              const float* __restrict__ W_ih,
              const float* __restrict__ W_hh,
              const float* __restrict__ b_ih,
              const float* __restrict__ b_hh,
              const float* __restrict__ fc_w,
              const float* __restrict__ fc_b,
              float* __restrict__ out)
{
    // 16-deep x ring + double-buffered h row; pads [13..15] stay zero.
    __shared__ __align__(16) float xring[16][16];
    __shared__ __align__(16) float hbuf[2][16];

    const int lane = threadIdx.x & 31;
    const int seq  = blockIdx.x;
    const float* xb = x + (size_t)seq * TT * 13;
    float* ob = out + (size_t)seq * TT;

    const unsigned haddr0 = (unsigned)__cvta_generic_to_shared(&hbuf[0][0]);
    const unsigned haddr1 = (unsigned)__cvta_generic_to_shared(&hbuf[1][0]);

    // Zero ring + h buffers once (cp.async only writes [0..12]).
    #pragma unroll
    for (int i = 0; i < 8; i++)
        reinterpret_cast<float*>(xring)[i * 32 + lane] = 0.0f;
    if (lane < 16) { hbuf[0][lane] = 0.0f; hbuf[1][lane] = 0.0f; }

    // Lane L<26: A = gate L (sigmoid: i for L<13, f for L>=13),
    // B = gate 26+L (g=tanh for L<13, o=sigmoid for 13<=L<26).
    // Lane 26: B-dot is the FC head (x-weights 0, h-weights 0.5*fc_w, bias 0.5*fc_b).
    // Sigmoid pre-scale 0.5 folded into weights: act = m*tanh(pre) + a.
    float wiA[13], whAs[13], wiB[13], whBs[13];
    float biasA = 0.0f, biasB = 0.0f;
    {
        const bool g26 = (lane < 26);
        const float sA = 0.5f;
        const float sB = (lane < 13) ? 1.0f : 0.5f;
        const int rA = g26 ? lane : 0;
        const int rB = g26 ? lane + 26 : 0;
        #pragma unroll
        for (int k = 0; k < 13; k++) {
            wiA[k]  = g26 ? sA * W_ih[rA * 13 + k] : 0.0f;
            whAs[k] = g26 ? sA * W_hh[rA * 13 + k] : 0.0f;
            wiB[k]  = g26 ? sB * W_ih[rB * 13 + k] : 0.0f;
            whBs[k] = g26 ? sB * W_hh[rB * 13 + k] : 0.0f;
        }
        if (g26) {
            biasA = sA * (b_ih[rA] + b_hh[rA]);
            biasB = sB * (b_ih[rB] + b_hh[rB]);
        }
        if (lane == 26) {
            #pragma unroll
            for (int k = 0; k < 13; k++) { wiB[k] = 0.0f; whBs[k] = 0.5f * fc_w[k]; }
            biasB = 0.5f * fc_b[0];
        }
    }

    // Pack all weights pairwise over k (7 pairs, last padded with 0).
    ull wxA[7], whA[7], wxB[7], whB[7];
    #pragma unroll
    for (int p = 0; p < 6; p++) {
        wxA[p] = pk(wiA[2*p],  wiA[2*p+1]);
        whA[p] = pk(whAs[2*p], whAs[2*p+1]);
        wxB[p] = pk(wiB[2*p],  wiB[2*p+1]);
        whB[p] = pk(whBs[2*p], whBs[2*p+1]);
    }
    wxA[6] = pk(wiA[12],  0.0f);
    whA[6] = pk(whAs[12], 0.0f);
    wxB[6] = pk(wiB[12],  0.0f);
    whB[6] = pk(whBs[12], 0.0f);

    const ull biasPA = pk(biasA, 0.0f);
    const ull biasPB = pk(biasB, 0.0f);
    const ull z64    = pk(0.0f, 0.0f);

    const float mB = (lane < 13) ? 1.0f : 0.5f;
    const float aB = (lane < 13) ? 0.0f : 0.5f;

    float h = 0.0f, c = 0.0f;

    // Prologue: stage rows 0..7 as ONE commit group.
    #pragma unroll
    for (int r = 0; r < 8; r++)
        if (lane < 13) cp_async4(&xring[r][lane], xb + r * 13 + lane);
    cp_commit();

// One LSTM step. SLOT: x-ring row (compile-time). RA/WA: h read/write smem addr.
// Each gate: 2 x-chains + 2 h-chains (depth <=4), joined by an add2 tree.
#define STEP(SLOT, RA, WA, TTC) do {                                           \
    ull hp[7];                                                                 \
    lds_hpairs((RA), hp);                                                      \
    const double2* xr = reinterpret_cast<const double2*>(&xring[(SLOT)][0]);   \
    const double2 q0 = xr[0], q1 = xr[1], q2 = xr[2];                          \
    const double  q3 = *reinterpret_cast<const double*>(&xring[(SLOT)][12]);   \
    const ull xp0 = d2l(q0.x), xp1 = d2l(q0.y), xp2 = d2l(q1.x),               \
              xp3 = d2l(q1.y), xp4 = d2l(q2.x), xp5 = d2l(q2.y),               \
              xp6 = d2l(q3);                                                   \
    /* gate A */                                                               \
    ull xa0 = fma2(xp0, wxA[0], biasPA);                                       \
    ull xa1 = fma2(xp1, wxA[1], z64);                                          \
    xa0 = fma2(xp2, wxA[2], xa0);                                              \
    xa1 = fma2(xp3, wxA[3], xa1);                                              \
    xa0 = fma2(xp4, wxA[4], xa0);                                              \
    xa1 = fma2(xp5, wxA[5], xa1);                                              \
    xa0 = fma2(xp6, wxA[6], xa0);                                              \
    ull ha0 = fma2(hp[0], whA[0], z64);                                        \
    ull ha1 = fma2(hp[1], whA[1], z64);                                        \
    ha0 = fma2(hp[2], whA[2], ha0);                                            \
    ha1 = fma2(hp[3], whA[3], ha1);                                            \
    ha0 = fma2(hp[4], whA[4], ha0);                                            \
    ha1 = fma2(hp[5], whA[5], ha1);                                            \
    ha0 = fma2(hp[6], whA[6], ha0);                                            \
    /* gate B */                                                               \
    ull xb0 = fma2(xp0, wxB[0], biasPB);                                       \
    ull xb1 = fma2(xp1, wxB[1], z64);                                          \
    xb0 = fma2(xp2, wxB[2], xb0);                                              \
    xb1 = fma2(xp3, wxB[3], xb1);                                              \
    xb0 = fma2(xp4, wxB[4], xb0);                                              \
    xb1 = fma2(xp5, wxB[5], xb1);                                              \
    xb0 = fma2(xp6, wxB[6], xb0);                                              \
    ull hb0 = fma2(hp[0], whB[0], z64);                                        \
    ull hb1 = fma2(hp[1], whB[1], z64);                                        \
    hb0 = fma2(hp[2], whB[2], hb0);                                            \
    hb1 = fma2(hp[3], whB[3], hb1);                                            \
    hb0 = fma2(hp[4], whB[4], hb0);                                            \
    hb1 = fma2(hp[5], whB[5], hb1);                                            \
    hb0 = fma2(hp[6], whB[6], hb0);                                            \
    ull sA = add2(add2(xa0, xa1), add2(ha0, ha1));                             \
    ull sB = add2(add2(xb0, xb1), add2(hb0, hb1));                             \
    float sa0, sa1, sb0, sb1;                                                  \
    upk(sA, sa0, sa1); upk(sB, sb0, sb1);                                      \
    const float preA = sa0 + sa1;                                              \
    const float preB = sb0 + sb1;                                              \
    const float actA = fmaf(0.5f, tanhap(preA), 0.5f);                         \
    const float actB = fmaf(mB,   tanhap(preB), aB);                           \
    if (lane == 26 && (TTC) > 0) ob[(TTC) - 1] = actB;                         \
    const float fg = __shfl_sync(FULLM, actA, (lane + 13) & 31);               \
    const float og = __shfl_sync(FULLM, actB, (lane + 13) & 31);               \
    c = fmaf(fg, c, actA * actB);                                              \
    h = og * tanhap(c);                                                        \
    if (lane < 13) sts_h((WA) + lane * 4, h);                                  \
} while (0)

    for (int t = 0; t < TT; t += 16) {
        // Half 0: prefetch rows t+8..t+15 into slots 8..15; process slots 0..7.
        #pragma unroll
        for (int r = 0; r < 8; r++)
            if (lane < 13 && t + 8 + r < TT)
                cp_async4(&xring[8 + r][lane], xb + (size_t)(t + 8 + r) * 13 + lane);
        cp_commit();
        cp_wait1();          // rows t..t+7 complete
        __syncwarp();        // one cp visibility sync per 8 steps
        STEP(0, haddr1, haddr0, t + 0);
        STEP(1, haddr0, haddr1, t + 1);
        STEP(2, haddr1, haddr0, t + 2);
        STEP(3, haddr0, haddr1, t + 3);
        STEP(4, haddr1, haddr0, t + 4);
        STEP(5, haddr0, haddr1, t + 5);
        STEP(6, haddr1, haddr0, t + 6);
        STEP(7, haddr0, haddr1, t + 7);

        // Half 1: prefetch rows t+16..t+23 into slots 0..7; process slots 8..15.
        #pragma unroll
        for (int r = 0; r < 8; r++)
            if (lane < 13 && t + 16 + r < TT)
                cp_async4(&xring[r][lane], xb + (size_t)(t + 16 + r) * 13 + lane);
        cp_commit();
        cp_wait1();          // rows t+8..t+15 complete
        __syncwarp();
        STEP( 8, haddr1, haddr0, t +  8);
        STEP( 9, haddr0, haddr1, t +  9);
        STEP(10, haddr1, haddr0, t + 10);
        STEP(11, haddr0, haddr1, t + 11);
        STEP(12, haddr1, haddr0, t + 12);
        STEP(13, haddr0, haddr1, t + 13);
        STEP(14, haddr1, haddr0, t + 14);
        STEP(15, haddr0, haddr1, t + 15);
    }
#undef STEP

    // Tail: ob[TT-1] = sigm(fc(h_{TT-1})). Step 2047 wrote hbuf[1].
    __syncwarp();
    {
        float hk[13];
        #pragma unroll
        for (int k = 0; k < 13; k++) hk[k] = hbuf[1][k];
        float s0 = biasB, s1 = 0.0f, s2 = 0.0f, s3 = 0.0f;
        #pragma unroll
        for (int k = 0; k < 13; k++) {
            switch (k & 3) {
                case 0: s0 = fmaf(hk[k], whBs[k], s0); break;
                case 1: s1 = fmaf(hk[k], whBs[k], s1); break;
                case 2: s2 = fmaf(hk[k], whBs[k], s2); break;
                case 3: s3 = fmaf(hk[k], whBs[k], s3); break;
            }
        }
        const float pre  = (s0 + s1) + (s2 + s3);
        const float outv = fmaf(0.5f, tanhap(pre), 0.5f);
        if (lane == 26) ob[TT - 1] = outv;
    }
}

extern "C" void kernel_launch(void* const* d_in, const int* in_sizes, int n_in,
                              void* d_out, int out_size) {
    (void)in_sizes; (void)n_in; (void)out_size;
    const float* x    = (const float*)d_in[0];
    const float* W_ih = (const float*)d_in[1];
    const float* W_hh = (const float*)d_in[2];
    const float* b_ih = (const float*)d_in[3];
    const float* b_hh = (const float*)d_in[4];
    const float* fc_w = (const float*)d_in[5];
    const float* fc_b = (const float*)d_in[6];
    float* out = (float*)d_out;

    lstm_warpseq6<<<NB, 32>>>(x, W_ih, W_hh, b_ih, b_hh, fc_w, fc_b, out);
}